// round 7
// baseline (speedup 1.0000x reference)
#include <cuda_runtime.h>
#include <cuda_bf16.h>
#include <cstdint>

// ---------------------------------------------------------------------------
// Problem constants
// ---------------------------------------------------------------------------
#define BATCH   32
#define NAGENT  64
#define BN      2048
#define CIN0    16
#define HW0     30
#define FLAT    7744
#define EDIM    128
#define ADIM    5

// Conv smem layout (floats), padded strides for conflict-free LDS.64:
//   in0 : 16 x 30 rows x stride 30  @ 13440   (14400)
//   out0: 16 x 28 rows x stride 30  @ 0       (13440)
//   out1: 32 x 26 rows x stride 26  @ 13440   (21632)
//   out2: 16 x 24 rows x stride 26  @ 0       ( 9984)
//   out3: 16 x 22 rows x stride 22  @ 9984    ( 7744)
#define OFF_IN0    13440
#define OFF_OUT0   0
#define OFF_OUT1   13440
#define OFF_OUT2   0
#define OFF_OUT3   9984
#define SM_FLOATS  35072
#define WOFF_U64   17536          // u64 index of weight region (= 35072 floats)
#define WREG_U64   4608           // max stage weights (32*16*9) in u64

#define CONV_THREADS 224

// ---------------------------------------------------------------------------
// Scratch
// ---------------------------------------------------------------------------
__device__ float g_flat [ (size_t)BN * FLAT ];
__device__ float g_acc0 [ BN * EDIM ];
__device__ float g_h    [ BN * EDIM ];

// ---------------------------------------------------------------------------
// f32x2 packed-math helpers
// ---------------------------------------------------------------------------
typedef unsigned long long u64;

__device__ __forceinline__ u64 pk2(float lo, float hi) {
    u64 r; asm("mov.b64 %0, {%1, %2};" : "=l"(r) : "f"(lo), "f"(hi)); return r;
}
__device__ __forceinline__ u64 pk1(float v) {
    u64 r; asm("mov.b64 %0, {%1, %1};" : "=l"(r) : "f"(v)); return r;
}
__device__ __forceinline__ u64 ffma2(u64 a, u64 b, u64 c) {
    u64 d; asm("fma.rn.f32x2 %0, %1, %2, %3;" : "=l"(d) : "l"(a), "l"(b), "l"(c));
    return d;
}
__device__ __forceinline__ void upk2(u64 v, float& lo, float& hi) {
    asm("mov.b64 {%0, %1}, %2;" : "=f"(lo), "=f"(hi) : "l"(v));
}

// ---------------------------------------------------------------------------
// Duplicated weight pack: dst[i] = {w[i], w[i]} (layout [co][ci][9] preserved)
// ---------------------------------------------------------------------------
template<int N>
__device__ __forceinline__ void pack_w_dup(u64* __restrict__ dst,
                                           const float* __restrict__ w,
                                           int tid, int nthr)
{
    for (int i = tid; i < N; i += nthr) dst[i] = pk1(__ldg(&w[i]));
}

// ---------------------------------------------------------------------------
// One conv item: 1 output channel, 2 output rows, NCOL pixel-pairs.
// Lanes of f32x2 = adjacent pixels; weights duplicated in smem.
// ---------------------------------------------------------------------------
template<int IHW, int OHW, int CI, int SIN, int SOUT, int NCOL>
__device__ __forceinline__ void conv_item(const float* __restrict__ in,
                                          float* __restrict__ out,
                                          const u64* __restrict__ wdup,
                                          const float* __restrict__ bias,
                                          int co, int y2, int x0)
{
    const int y = 2 * y2;
    u64 acc0[NCOL], acc1[NCOL];
    u64 binit = pk1(__ldg(&bias[co]));
    #pragma unroll
    for (int c = 0; c < NCOL; c++) { acc0[c] = binit; acc1[c] = binit; }

    const u64* wci = wdup + co * (CI * 9);

    for (int ci = 0; ci < CI; ci++) {
        u64 w[9];
        #pragma unroll
        for (int i = 0; i < 9; i++) w[i] = wci[ci * 9 + i];

        const float* plane = in + ci * (IHW * SIN);
        #pragma unroll
        for (int ir = 0; ir < 4; ir++) {
            const u64* r = (const u64*)(plane + (y + ir) * SIN + x0);
            u64 A = r[0];
            #pragma unroll
            for (int c = 0; c < NCOL; c++) {
                u64 C = r[c + 1];
                float alo, ahi, clo, chi;
                upk2(A, alo, ahi);
                upk2(C, clo, chi);
                u64 B = pk2(ahi, clo);
                if (ir < 3) {
                    acc0[c] = ffma2(A, w[ir * 3 + 0], acc0[c]);
                    acc0[c] = ffma2(B, w[ir * 3 + 1], acc0[c]);
                    acc0[c] = ffma2(C, w[ir * 3 + 2], acc0[c]);
                }
                if (ir > 0) {
                    acc1[c] = ffma2(A, w[(ir - 1) * 3 + 0], acc1[c]);
                    acc1[c] = ffma2(B, w[(ir - 1) * 3 + 1], acc1[c]);
                    acc1[c] = ffma2(C, w[(ir - 1) * 3 + 2], acc1[c]);
                }
                A = C;
            }
        }
    }

    float* o0 = out + (co * OHW + y    ) * SOUT + x0;
    float* o1 = out + (co * OHW + y + 1) * SOUT + x0;
    #pragma unroll
    for (int c = 0; c < NCOL; c++) {
        float lo, hi;
        upk2(acc0[c], lo, hi);
        o0[2*c]   = fmaxf(lo, 0.0f);
        o0[2*c+1] = fmaxf(hi, 0.0f);
        upk2(acc1[c], lo, hi);
        o1[2*c]   = fmaxf(lo, 0.0f);
        o1[2*c+1] = fmaxf(hi, 0.0f);
    }
}

template<int IHW, int OHW, int CI, int CO, int SIN, int SOUT, int W0, int W1>
__device__ __forceinline__ void conv_stage(const float* __restrict__ in,
                                           float* __restrict__ out,
                                           const u64* __restrict__ wdup,
                                           const float* __restrict__ bias,
                                           int tid, int nthr)
{
    constexpr int NY2 = OHW / 2;
    // segment 0: columns [0, W0)
    for (int p = tid; p < CO * NY2; p += nthr) {
        int co = p / NY2, y2 = p - co * NY2;
        conv_item<IHW, OHW, CI, SIN, SOUT, W0/2>(in, out, wdup, bias, co, y2, 0);
    }
    // segment 1: columns [W0, OHW)
    for (int p = tid; p < CO * NY2; p += nthr) {
        int co = p / NY2, y2 = p - co * NY2;
        conv_item<IHW, OHW, CI, SIN, SOUT, W1/2>(in, out, wdup, bias, co, y2, W0);
    }
}

__global__ __launch_bounds__(CONV_THREADS, 1)
void conv_fused_kernel(const float* __restrict__ states,
                       const float* __restrict__ cw0, const float* __restrict__ cb0,
                       const float* __restrict__ cw1, const float* __restrict__ cb1,
                       const float* __restrict__ cw2, const float* __restrict__ cb2,
                       const float* __restrict__ cw3, const float* __restrict__ cb3,
                       float* __restrict__ flat)
{
    extern __shared__ float s[];
    u64* wpk = (u64*)(s) + WOFF_U64;
    const int agent = blockIdx.x;
    const int tid = threadIdx.x, nthr = blockDim.x;

    // load input image [16,30,30] (dense, stride 30)
    {
        const float4* src = (const float4*)(states + (size_t)agent * (CIN0*HW0*HW0));
        float4* dst = (float4*)(s + OFF_IN0);
        for (int i = tid; i < (CIN0*HW0*HW0)/4; i += nthr) dst[i] = src[i];
    }
    pack_w_dup<16*16*9>(wpk, cw0, tid, nthr);
    __syncthreads();

    conv_stage<30,28,16,16,30,30,14,14>(s + OFF_IN0 , s + OFF_OUT0, wpk, cb0, tid, nthr);
    __syncthreads();
    pack_w_dup<32*16*9>(wpk, cw1, tid, nthr);
    __syncthreads();

    conv_stage<28,26,16,32,30,26,14,12>(s + OFF_OUT0, s + OFF_OUT1, wpk, cb1, tid, nthr);
    __syncthreads();
    pack_w_dup<16*32*9>(wpk, cw2, tid, nthr);
    __syncthreads();

    conv_stage<26,24,32,16,26,26,12,12>(s + OFF_OUT1, s + OFF_OUT2, wpk, cb2, tid, nthr);
    __syncthreads();
    pack_w_dup<16*16*9>(wpk, cw3, tid, nthr);
    __syncthreads();

    conv_stage<24,22,16,16,26,22,12,10>(s + OFF_OUT2, s + OFF_OUT3, wpk, cb3, tid, nthr);
    __syncthreads();

    // write flat features (out3 dense [16][22][22])
    {
        float4* fo = (float4*)(flat + (size_t)agent * FLAT);
        const float4* fs = (const float4*)(s + OFF_OUT3);
        for (int i = tid; i < FLAT/4; i += nthr) fo[i] = fs[i];
    }
}

// ---------------------------------------------------------------------------
// MLP0 split-K (unchanged)
// ---------------------------------------------------------------------------
#define KSPLIT  8
#define KCHUNK  968

__global__ void mlp0_splitk_kernel(const float* __restrict__ A,
                                   const float* __restrict__ W,
                                   float* __restrict__ Cacc)
{
    __shared__ float As[8 * 68];
    __shared__ float Ws[8 * 128];
    const int t  = threadIdx.x;
    const int kz = blockIdx.x;
    const int m0 = blockIdx.y * 64;
    const int kstart = kz * KCHUNK;
    const int tx = t & 31, ty = t >> 5;

    u64 acc[8][2];
    #pragma unroll
    for (int r = 0; r < 8; r++) { acc[r][0] = 0ull; acc[r][1] = 0ull; }

    for (int kk = 0; kk < KCHUNK; kk += 8) {
        __syncthreads();
        {
            int e = t * 2;
            int m = e >> 3, k = e & 7;
            const float* ap = A + (size_t)(m0 + m) * FLAT + kstart + kk + k;
            As[ k      * 68 + m] = ap[0];
            As[(k + 1) * 68 + m] = ap[1];
        }
        {
            int e = t * 4;
            int k = e >> 7, col = e & 127;
            *(float4*)&Ws[k * 128 + col] =
                *(const float4*)&W[(size_t)(kstart + kk + k) * EDIM + col];
        }
        __syncthreads();
        #pragma unroll
        for (int k = 0; k < 8; k++) {
            u64 B0 = *(const u64*)&Ws[k * 128 + tx * 4];
            u64 B1 = *(const u64*)&Ws[k * 128 + tx * 4 + 2];
            float4 a0 = *(float4*)&As[k * 68 + ty * 8];
            float4 a1 = *(float4*)&As[k * 68 + ty * 8 + 4];
            float av[8] = {a0.x,a0.y,a0.z,a0.w,a1.x,a1.y,a1.z,a1.w};
            #pragma unroll
            for (int r = 0; r < 8; r++) {
                u64 ar = pk1(av[r]);
                acc[r][0] = ffma2(ar, B0, acc[r][0]);
                acc[r][1] = ffma2(ar, B1, acc[r][1]);
            }
        }
    }
    #pragma unroll
    for (int r = 0; r < 8; r++) {
        int m = m0 + ty * 8 + r;
        float v0, v1, v2, v3;
        upk2(acc[r][0], v0, v1);
        upk2(acc[r][1], v2, v3);
        atomicAdd(&Cacc[(size_t)m * EDIM + tx * 4 + 0], v0);
        atomicAdd(&Cacc[(size_t)m * EDIM + tx * 4 + 1], v1);
        atomicAdd(&Cacc[(size_t)m * EDIM + tx * 4 + 2], v2);
        atomicAdd(&Cacc[(size_t)m * EDIM + tx * 4 + 3], v3);
    }
}

// ---------------------------------------------------------------------------
// 32-row x 128 GEMM helper (256 threads): each thread 4 rows x 4 cols
// ---------------------------------------------------------------------------
__device__ __forceinline__ void gemm32(const float* __restrict__ sIn,
                                       float* __restrict__ sOut,
                                       float* __restrict__ sW,
                                       const float* __restrict__ W,
                                       const float* __restrict__ bias,
                                       int relu, int t)
{
    __syncthreads();
    for (int i = t * 4; i < 128 * 128; i += 1024)
        *(float4*)&sW[i] = *(const float4*)&W[i];
    __syncthreads();

    const int tx = t & 31;
    const int ry = (t >> 5) * 4;
    u64 acc[4][2];
    u64 b0i = bias ? pk2(bias[tx*4+0], bias[tx*4+1]) : 0ull;
    u64 b1i = bias ? pk2(bias[tx*4+2], bias[tx*4+3]) : 0ull;
    #pragma unroll
    for (int r = 0; r < 4; r++) { acc[r][0] = b0i; acc[r][1] = b1i; }

    #pragma unroll 4
    for (int k = 0; k < 128; k++) {
        u64 B0 = *(const u64*)&sW[k * 128 + tx * 4];
        u64 B1 = *(const u64*)&sW[k * 128 + tx * 4 + 2];
        #pragma unroll
        for (int r = 0; r < 4; r++) {
            u64 ar = pk1(sIn[(ry + r) * 128 + k]);
            acc[r][0] = ffma2(ar, B0, acc[r][0]);
            acc[r][1] = ffma2(ar, B1, acc[r][1]);
        }
    }
    #pragma unroll
    for (int r = 0; r < 4; r++) {
        float v[4];
        upk2(acc[r][0], v[0], v[1]);
        upk2(acc[r][1], v[2], v[3]);
        #pragma unroll
        for (int c = 0; c < 4; c++)
            if (relu) v[c] = fmaxf(v[c], 0.0f);
        *(float4*)&sOut[(ry + r) * 128 + tx * 4] = *(float4*)v;
    }
}

// ---------------------------------------------------------------------------
// K1: pre-GCN chain, grid = 64, 32-row tiles
// ---------------------------------------------------------------------------
__global__ __launch_bounds__(256, 1)
void pre_gcn_kernel(const float* __restrict__ acc0,
                    const float* __restrict__ mb0,
                    const float* __restrict__ mw1, const float* __restrict__ mb1,
                    const float* __restrict__ mw2, const float* __restrict__ mb2,
                    const float* __restrict__ gw,
                    float* __restrict__ h)
{
    extern __shared__ float s[];
    float* sA = s;             // 32*128
    float* sB = s + 4096;      // 32*128
    float* sW = s + 8192;      // 128*128
    const int t = threadIdx.x;
    const size_t base = (size_t)blockIdx.x * 32 * EDIM;

    for (int i = t; i < 4096; i += 256) {
        int k = i & 127;
        sA[i] = fmaxf(acc0[base + i] + mb0[k], 0.0f);
    }

    gemm32(sA, sB, sW, mw1, mb1, 1, t);
    gemm32(sB, sA, sW, mw2, mb2, 0, t);
    gemm32(sA, sB, sW, gw,  nullptr, 0, t);

    __syncthreads();
    for (int i = t; i < 4096; i += 256) h[base + i] = sB[i];
}

// ---------------------------------------------------------------------------
// K2: GCN aggregation + DQN head, grid = (32 batches, 2 halves of 32 agents)
// ---------------------------------------------------------------------------
__global__ __launch_bounds__(256, 1)
void gcn_tail_kernel(const float* __restrict__ h,
                     const float* __restrict__ gb,
                     const float* __restrict__ fw0, const float* __restrict__ fb0,
                     const float* __restrict__ fw1, const float* __restrict__ fb1,
                     const float* __restrict__ fw2, const float* __restrict__ fb2,
                     const float* __restrict__ adj,
                     const int* __restrict__ inact,
                     float* __restrict__ out)
{
    extern __shared__ float s[];
    float* sH = s;            // 64*128
    float* sX = s + 8192;     // 32*128
    float* sY = s + 12288;    // 32*128
    float* sW = s + 16384;    // 128*128; adj(4096)+dis(64) scratch
    const int b = blockIdx.x, t = threadIdx.x;
    const int j0 = blockIdx.y * 32;
    const size_t row0 = (size_t)b * NAGENT;

    for (int i = t; i < 8192; i += 256) sH[i] = h[row0 * EDIM + i];
    for (int i = t; i < 4096; i += 256) sW[i] = adj[(size_t)b * 4096 + i];
    __syncthreads();
    if (t < 64) {
        float d = 0.f;
        for (int i = 0; i < 64; i++) d += sW[i * 64 + t];
        sW[4096 + t] = (d > 0.f) ? rsqrtf(fmaxf(d, 1e-30f)) : 0.f;
    }
    __syncthreads();
    for (int i = t; i < 4096; i += 256) {
        int r = i >> 6, c = i & 63;
        sW[i] *= sW[4096 + r] * sW[4096 + c];
    }
    __syncthreads();
    for (int o = t; o < 4096; o += 256) {
        int jl = o >> 7, d = o & 127;
        int j = j0 + jl;
        float a = gb[d];
        #pragma unroll 8
        for (int i = 0; i < 64; i++)
            a = fmaf(sW[i * 64 + j], sH[i * 128 + d], a);
        sX[o] = a;
    }

    gemm32(sX, sY, sW, fw0, fb0, 1, t);   // q1
    gemm32(sY, sX, sW, fw1, fb1, 1, t);   // q2

    __syncthreads();
    for (int p = t; p < 32 * ADIM; p += 256) {
        int row = p / ADIM, a = p - row * ADIM;
        float acc = fb2[a];
        #pragma unroll 8
        for (int k = 0; k < EDIM; k++)
            acc = fmaf(sX[row * 128 + k], __ldg(&fw2[k * ADIM + a]), acc);
        size_t grow = row0 + j0 + row;
        bool z = (inact[grow] != 0);
        out[grow * ADIM + a] = z ? 0.f : acc;
    }
}

__global__ void zero_kernel(float* __restrict__ p, int n)
{
    int i = blockIdx.x * blockDim.x + threadIdx.x;
    if (i < n) p[i] = 0.f;
}

// ---------------------------------------------------------------------------
// Launch
// ---------------------------------------------------------------------------
extern "C" void kernel_launch(void* const* d_in, const int* in_sizes, int n_in,
                              void* d_out, int out_size)
{
    (void)in_sizes; (void)n_in; (void)out_size;
    const float* states = (const float*)d_in[0];
    const float* adj    = (const float*)d_in[1];
    const int*   inact  = (const int*)d_in[2];
    const float* cw0 = (const float*)d_in[3];  const float* cb0 = (const float*)d_in[4];
    const float* cw1 = (const float*)d_in[5];  const float* cb1 = (const float*)d_in[6];
    const float* cw2 = (const float*)d_in[7];  const float* cb2 = (const float*)d_in[8];
    const float* cw3 = (const float*)d_in[9];  const float* cb3 = (const float*)d_in[10];
    const float* mw0 = (const float*)d_in[11]; const float* mb0 = (const float*)d_in[12];
    const float* mw1 = (const float*)d_in[13]; const float* mb1 = (const float*)d_in[14];
    const float* mw2 = (const float*)d_in[15]; const float* mb2 = (const float*)d_in[16];
    const float* gw  = (const float*)d_in[17]; const float* gb  = (const float*)d_in[18];
    const float* fw0 = (const float*)d_in[19]; const float* fb0 = (const float*)d_in[20];
    const float* fw1 = (const float*)d_in[21]; const float* fb1 = (const float*)d_in[22];
    const float* fw2 = (const float*)d_in[23]; const float* fb2 = (const float*)d_in[24];
    float* out = (float*)d_out;

    float *p_flat, *p_acc0, *p_h;
    cudaGetSymbolAddress((void**)&p_flat, g_flat);
    cudaGetSymbolAddress((void**)&p_acc0, g_acc0);
    cudaGetSymbolAddress((void**)&p_h,    g_h);

    const int convSmem = SM_FLOATS * 4 + WREG_U64 * 8;          // 177152 B
    const int preSmem  = (4096 + 4096 + 16384) * 4;             //  98304 B
    const int tailSmem = (8192 + 4096 + 4096 + 16384) * 4;      // 131072 B
    cudaFuncSetAttribute(conv_fused_kernel, cudaFuncAttributeMaxDynamicSharedMemorySize, convSmem);
    cudaFuncSetAttribute(pre_gcn_kernel,    cudaFuncAttributeMaxDynamicSharedMemorySize, preSmem);
    cudaFuncSetAttribute(gcn_tail_kernel,   cudaFuncAttributeMaxDynamicSharedMemorySize, tailSmem);

    zero_kernel<<<(BN*EDIM + 255)/256, 256>>>(p_acc0, BN*EDIM);

    conv_fused_kernel<<<BN, CONV_THREADS, convSmem>>>(states, cw0, cb0, cw1, cb1,
                                                      cw2, cb2, cw3, cb3, p_flat);

    mlp0_splitk_kernel<<<dim3(KSPLIT, BN/64), 256>>>(p_flat, mw0, p_acc0);

    pre_gcn_kernel<<<BN/32, 256, preSmem>>>(p_acc0, mb0, mw1, mb1, mw2, mb2, gw, p_h);

    gcn_tail_kernel<<<dim3(BATCH, 2), 256, tailSmem>>>(p_h, gb, fw0, fb0, fw1, fb1,
                                                       fw2, fb2, adj, inact, out);
}

// round 8
// speedup vs baseline: 1.2048x; 1.2048x over previous
#include <cuda_runtime.h>
#include <cuda_bf16.h>
#include <cstdint>

// ---------------------------------------------------------------------------
// Problem constants
// ---------------------------------------------------------------------------
#define BATCH   32
#define NAGENT  64
#define BN      2048
#define CIN0    16
#define HW0     30
#define FLAT    7744
#define EDIM    128
#define ADIM    5

// Conv smem ping-pong layout (floats)  — identical to round 6
#define SM_TOTAL   34176
#define OFF_IN0    0
#define OFF_OUT0   21632
#define OFF_OUT1   0
#define OFF_OUT2   24960
#define OFF_OUT3   0

// Packed-weight smem region (u64 units), appended after float region
#define WPK0   0                 // 8*16*9  = 1152
#define WPK1   1152              // 16*16*9 = 2304
#define WPK2   3456              // 8*32*9  = 2304
#define WPK3   5760              // 8*16*9  = 1152
#define WPK_TOTAL 6912           // u64s -> 55296 bytes

#define CONV_THREADS 448

// ---------------------------------------------------------------------------
// Scratch
// ---------------------------------------------------------------------------
__device__ float g_flat [ (size_t)BN * FLAT ];
__device__ float g_acc0 [ BN * EDIM ];
__device__ float g_h    [ BN * EDIM ];

// ---------------------------------------------------------------------------
// f32x2 packed-math helpers
// ---------------------------------------------------------------------------
typedef unsigned long long u64;

__device__ __forceinline__ u64 pk2(float lo, float hi) {
    u64 r; asm("mov.b64 %0, {%1, %2};" : "=l"(r) : "f"(lo), "f"(hi)); return r;
}
__device__ __forceinline__ u64 pk1(float v) {
    u64 r; asm("mov.b64 %0, {%1, %1};" : "=l"(r) : "f"(v)); return r;
}
__device__ __forceinline__ u64 ffma2(u64 a, u64 b, u64 c) {
    u64 d; asm("fma.rn.f32x2 %0, %1, %2, %3;" : "=l"(d) : "l"(a), "l"(b), "l"(c));
    return d;
}
__device__ __forceinline__ void upk2(u64 v, float& lo, float& hi) {
    asm("mov.b64 {%0, %1}, %2;" : "=f"(lo), "=f"(hi) : "l"(v));
}

// ---------------------------------------------------------------------------
// Cooperative weight packing: w[CO][CI][3][3] -> wpk[(CO/2)][CI*9] u64 pairs
// ---------------------------------------------------------------------------
template<int CI, int CO>
__device__ __forceinline__ void pack_w(u64* __restrict__ dst,
                                       const float* __restrict__ w,
                                       int tid, int nthr)
{
    constexpr int PER = CI * 9;
    constexpr int N   = (CO / 2) * PER;
    for (int i = tid; i < N; i += nthr) {
        int pair = i / PER;
        int r    = i - pair * PER;
        dst[i] = pk2(__ldg(&w[(2 * pair    ) * PER + r]),
                     __ldg(&w[(2 * pair + 1) * PER + r]));
    }
}

// ---------------------------------------------------------------------------
// Conv stage: 2 output channels x HALF row per work item, weights from smem.
// Channel-pair f32x2 lanes (proven R6 shape); half rows double item count
// so 448 threads (3.5 warps/SMSP) stay busy and hide LDS latency.
// ---------------------------------------------------------------------------
template<int CI, int CO, int IHW, int OHW>
__device__ __forceinline__ void conv_stage2h(const float* __restrict__ in,
                                             float* __restrict__ out,
                                             const u64* __restrict__ wpk,
                                             const float* __restrict__ bias,
                                             int tid, int nthr)
{
    constexpr int HALF  = OHW / 2;
    constexpr int ITEMS = (CO / 2) * OHW * 2;
    for (int p = tid; p < ITEMS; p += nthr) {
        int co2 = p / (OHW * 2);
        int rem = p - co2 * (OHW * 2);
        int y   = rem >> 1;
        int x0  = (rem & 1) * HALF;

        u64 acc[HALF];
        u64 binit = pk2(__ldg(&bias[2 * co2]), __ldg(&bias[2 * co2 + 1]));
        #pragma unroll
        for (int x = 0; x < HALF; x++) acc[x] = binit;

        const u64* wp0 = wpk + co2 * (CI * 9);

        for (int ci = 0; ci < CI; ci++) {
            #pragma unroll
            for (int ky = 0; ky < 3; ky++) {
                const u64* wp = wp0 + ci * 9 + ky * 3;
                u64 W0 = wp[0];
                u64 W1 = wp[1];
                u64 W2 = wp[2];
                const float* r = in + (ci * IHW + y + ky) * IHW + x0;
                u64 b0 = pk1(r[0]);
                u64 b1 = pk1(r[1]);
                #pragma unroll
                for (int x = 0; x < HALF; x++) {
                    u64 b2 = pk1(r[x + 2]);
                    acc[x] = ffma2(b0, W0, acc[x]);
                    acc[x] = ffma2(b1, W1, acc[x]);
                    acc[x] = ffma2(b2, W2, acc[x]);
                    b0 = b1; b1 = b2;
                }
            }
        }
        float* oA = out + (2 * co2 * OHW + y) * OHW + x0;
        float* oB = out + ((2 * co2 + 1) * OHW + y) * OHW + x0;
        #pragma unroll
        for (int x = 0; x < HALF; x++) {
            float lo, hi; upk2(acc[x], lo, hi);
            oA[x] = fmaxf(lo, 0.0f);
            oB[x] = fmaxf(hi, 0.0f);
        }
    }
}

__global__ __launch_bounds__(CONV_THREADS, 1)
void conv_fused_kernel(const float* __restrict__ states,
                       const float* __restrict__ cw0, const float* __restrict__ cb0,
                       const float* __restrict__ cw1, const float* __restrict__ cb1,
                       const float* __restrict__ cw2, const float* __restrict__ cb2,
                       const float* __restrict__ cw3, const float* __restrict__ cb3,
                       float* __restrict__ flat)
{
    extern __shared__ float s[];
    u64* wpk = (u64*)(s + SM_TOTAL);
    const int agent = blockIdx.x;
    const int tid = threadIdx.x, nthr = blockDim.x;

    // pack all conv weights into smem (u64 channel-pairs)
    pack_w<16,16>(wpk + WPK0, cw0, tid, nthr);
    pack_w<16,32>(wpk + WPK1, cw1, tid, nthr);
    pack_w<32,16>(wpk + WPK2, cw2, tid, nthr);
    pack_w<16,16>(wpk + WPK3, cw3, tid, nthr);

    // load input image [16,30,30]
    {
        const float4* src = (const float4*)(states + (size_t)agent * (CIN0*HW0*HW0));
        float4* dst = (float4*)(s + OFF_IN0);
        for (int i = tid; i < (CIN0*HW0*HW0)/4; i += nthr) dst[i] = src[i];
    }
    __syncthreads();
    conv_stage2h<16,16,30,28>(s + OFF_IN0 , s + OFF_OUT0, wpk + WPK0, cb0, tid, nthr);
    __syncthreads();
    conv_stage2h<16,32,28,26>(s + OFF_OUT0, s + OFF_OUT1, wpk + WPK1, cb1, tid, nthr);
    __syncthreads();
    conv_stage2h<32,16,26,24>(s + OFF_OUT1, s + OFF_OUT2, wpk + WPK2, cb2, tid, nthr);
    __syncthreads();
    conv_stage2h<16,16,24,22>(s + OFF_OUT2, s + OFF_OUT3, wpk + WPK3, cb3, tid, nthr);
    __syncthreads();
    {
        float4* fo = (float4*)(flat + (size_t)agent * FLAT);
        const float4* fs = (const float4*)(s + OFF_OUT3);
        for (int i = tid; i < FLAT/4; i += nthr) fo[i] = fs[i];
    }
}

// ---------------------------------------------------------------------------
// MLP0 split-K (unchanged)
// ---------------------------------------------------------------------------
#define KSPLIT  8
#define KCHUNK  968

__global__ void mlp0_splitk_kernel(const float* __restrict__ A,
                                   const float* __restrict__ W,
                                   float* __restrict__ Cacc)
{
    __shared__ float As[8 * 68];
    __shared__ float Ws[8 * 128];
    const int t  = threadIdx.x;
    const int kz = blockIdx.x;
    const int m0 = blockIdx.y * 64;
    const int kstart = kz * KCHUNK;
    const int tx = t & 31, ty = t >> 5;

    u64 acc[8][2];
    #pragma unroll
    for (int r = 0; r < 8; r++) { acc[r][0] = 0ull; acc[r][1] = 0ull; }

    for (int kk = 0; kk < KCHUNK; kk += 8) {
        __syncthreads();
        {
            int e = t * 2;
            int m = e >> 3, k = e & 7;
            const float* ap = A + (size_t)(m0 + m) * FLAT + kstart + kk + k;
            As[ k      * 68 + m] = ap[0];
            As[(k + 1) * 68 + m] = ap[1];
        }
        {
            int e = t * 4;
            int k = e >> 7, col = e & 127;
            *(float4*)&Ws[k * 128 + col] =
                *(const float4*)&W[(size_t)(kstart + kk + k) * EDIM + col];
        }
        __syncthreads();
        #pragma unroll
        for (int k = 0; k < 8; k++) {
            u64 B0 = *(const u64*)&Ws[k * 128 + tx * 4];
            u64 B1 = *(const u64*)&Ws[k * 128 + tx * 4 + 2];
            float4 a0 = *(float4*)&As[k * 68 + ty * 8];
            float4 a1 = *(float4*)&As[k * 68 + ty * 8 + 4];
            float av[8] = {a0.x,a0.y,a0.z,a0.w,a1.x,a1.y,a1.z,a1.w};
            #pragma unroll
            for (int r = 0; r < 8; r++) {
                u64 ar = pk1(av[r]);
                acc[r][0] = ffma2(ar, B0, acc[r][0]);
                acc[r][1] = ffma2(ar, B1, acc[r][1]);
            }
        }
    }
    #pragma unroll
    for (int r = 0; r < 8; r++) {
        int m = m0 + ty * 8 + r;
        float v0, v1, v2, v3;
        upk2(acc[r][0], v0, v1);
        upk2(acc[r][1], v2, v3);
        atomicAdd(&Cacc[(size_t)m * EDIM + tx * 4 + 0], v0);
        atomicAdd(&Cacc[(size_t)m * EDIM + tx * 4 + 1], v1);
        atomicAdd(&Cacc[(size_t)m * EDIM + tx * 4 + 2], v2);
        atomicAdd(&Cacc[(size_t)m * EDIM + tx * 4 + 3], v3);
    }
}

// ---------------------------------------------------------------------------
// 32-row x 128 GEMM helper (256 threads): each thread 4 rows x 4 cols
// ---------------------------------------------------------------------------
__device__ __forceinline__ void gemm32(const float* __restrict__ sIn,
                                       float* __restrict__ sOut,
                                       float* __restrict__ sW,
                                       const float* __restrict__ W,
                                       const float* __restrict__ bias,
                                       int relu, int t)
{
    __syncthreads();
    for (int i = t * 4; i < 128 * 128; i += 1024)
        *(float4*)&sW[i] = *(const float4*)&W[i];
    __syncthreads();

    const int tx = t & 31;
    const int ry = (t >> 5) * 4;
    u64 acc[4][2];
    u64 b0i = bias ? pk2(bias[tx*4+0], bias[tx*4+1]) : 0ull;
    u64 b1i = bias ? pk2(bias[tx*4+2], bias[tx*4+3]) : 0ull;
    #pragma unroll
    for (int r = 0; r < 4; r++) { acc[r][0] = b0i; acc[r][1] = b1i; }

    #pragma unroll 4
    for (int k = 0; k < 128; k++) {
        u64 B0 = *(const u64*)&sW[k * 128 + tx * 4];
        u64 B1 = *(const u64*)&sW[k * 128 + tx * 4 + 2];
        #pragma unroll
        for (int r = 0; r < 4; r++) {
            u64 ar = pk1(sIn[(ry + r) * 128 + k]);
            acc[r][0] = ffma2(ar, B0, acc[r][0]);
            acc[r][1] = ffma2(ar, B1, acc[r][1]);
        }
    }
    #pragma unroll
    for (int r = 0; r < 4; r++) {
        float v[4];
        upk2(acc[r][0], v[0], v[1]);
        upk2(acc[r][1], v[2], v[3]);
        #pragma unroll
        for (int c = 0; c < 4; c++)
            if (relu) v[c] = fmaxf(v[c], 0.0f);
        *(float4*)&sOut[(ry + r) * 128 + tx * 4] = *(float4*)v;
    }
}

// ---------------------------------------------------------------------------
// K1: pre-GCN chain, grid = 64, 32-row tiles
// ---------------------------------------------------------------------------
__global__ __launch_bounds__(256, 1)
void pre_gcn_kernel(const float* __restrict__ acc0,
                    const float* __restrict__ mb0,
                    const float* __restrict__ mw1, const float* __restrict__ mb1,
                    const float* __restrict__ mw2, const float* __restrict__ mb2,
                    const float* __restrict__ gw,
                    float* __restrict__ h)
{
    extern __shared__ float s[];
    float* sA = s;             // 32*128
    float* sB = s + 4096;      // 32*128
    float* sW = s + 8192;      // 128*128
    const int t = threadIdx.x;
    const size_t base = (size_t)blockIdx.x * 32 * EDIM;

    for (int i = t; i < 4096; i += 256) {
        int k = i & 127;
        sA[i] = fmaxf(acc0[base + i] + mb0[k], 0.0f);
    }

    gemm32(sA, sB, sW, mw1, mb1, 1, t);
    gemm32(sB, sA, sW, mw2, mb2, 0, t);
    gemm32(sA, sB, sW, gw,  nullptr, 0, t);

    __syncthreads();
    for (int i = t; i < 4096; i += 256) h[base + i] = sB[i];
}

// ---------------------------------------------------------------------------
// K2: GCN aggregation + DQN head, grid = (32 batches, 2 halves of 32 agents)
// ---------------------------------------------------------------------------
__global__ __launch_bounds__(256, 1)
void gcn_tail_kernel(const float* __restrict__ h,
                     const float* __restrict__ gb,
                     const float* __restrict__ fw0, const float* __restrict__ fb0,
                     const float* __restrict__ fw1, const float* __restrict__ fb1,
                     const float* __restrict__ fw2, const float* __restrict__ fb2,
                     const float* __restrict__ adj,
                     const int* __restrict__ inact,
                     float* __restrict__ out)
{
    extern __shared__ float s[];
    float* sH = s;            // 64*128
    float* sX = s + 8192;     // 32*128
    float* sY = s + 12288;    // 32*128
    float* sW = s + 16384;    // 128*128; adj(4096)+dis(64) scratch
    const int b = blockIdx.x, t = threadIdx.x;
    const int j0 = blockIdx.y * 32;
    const size_t row0 = (size_t)b * NAGENT;

    for (int i = t; i < 8192; i += 256) sH[i] = h[row0 * EDIM + i];
    for (int i = t; i < 4096; i += 256) sW[i] = adj[(size_t)b * 4096 + i];
    __syncthreads();
    if (t < 64) {
        float d = 0.f;
        for (int i = 0; i < 64; i++) d += sW[i * 64 + t];
        sW[4096 + t] = (d > 0.f) ? rsqrtf(fmaxf(d, 1e-30f)) : 0.f;
    }
    __syncthreads();
    for (int i = t; i < 4096; i += 256) {
        int r = i >> 6, c = i & 63;
        sW[i] *= sW[4096 + r] * sW[4096 + c];
    }
    __syncthreads();
    for (int o = t; o < 4096; o += 256) {
        int jl = o >> 7, d = o & 127;
        int j = j0 + jl;
        float a = gb[d];
        #pragma unroll 8
        for (int i = 0; i < 64; i++)
            a = fmaf(sW[i * 64 + j], sH[i * 128 + d], a);
        sX[o] = a;
    }

    gemm32(sX, sY, sW, fw0, fb0, 1, t);   // q1
    gemm32(sY, sX, sW, fw1, fb1, 1, t);   // q2

    __syncthreads();
    for (int p = t; p < 32 * ADIM; p += 256) {
        int row = p / ADIM, a = p - row * ADIM;
        float acc = fb2[a];
        #pragma unroll 8
        for (int k = 0; k < EDIM; k++)
            acc = fmaf(sX[row * 128 + k], __ldg(&fw2[k * ADIM + a]), acc);
        size_t grow = row0 + j0 + row;
        bool z = (inact[grow] != 0);
        out[grow * ADIM + a] = z ? 0.f : acc;
    }
}

__global__ void zero_kernel(float* __restrict__ p, int n)
{
    int i = blockIdx.x * blockDim.x + threadIdx.x;
    if (i < n) p[i] = 0.f;
}

// ---------------------------------------------------------------------------
// Launch
// ---------------------------------------------------------------------------
extern "C" void kernel_launch(void* const* d_in, const int* in_sizes, int n_in,
                              void* d_out, int out_size)
{
    (void)in_sizes; (void)n_in; (void)out_size;
    const float* states = (const float*)d_in[0];
    const float* adj    = (const float*)d_in[1];
    const int*   inact  = (const int*)d_in[2];
    const float* cw0 = (const float*)d_in[3];  const float* cb0 = (const float*)d_in[4];
    const float* cw1 = (const float*)d_in[5];  const float* cb1 = (const float*)d_in[6];
    const float* cw2 = (const float*)d_in[7];  const float* cb2 = (const float*)d_in[8];
    const float* cw3 = (const float*)d_in[9];  const float* cb3 = (const float*)d_in[10];
    const float* mw0 = (const float*)d_in[11]; const float* mb0 = (const float*)d_in[12];
    const float* mw1 = (const float*)d_in[13]; const float* mb1 = (const float*)d_in[14];
    const float* mw2 = (const float*)d_in[15]; const float* mb2 = (const float*)d_in[16];
    const float* gw  = (const float*)d_in[17]; const float* gb  = (const float*)d_in[18];
    const float* fw0 = (const float*)d_in[19]; const float* fb0 = (const float*)d_in[20];
    const float* fw1 = (const float*)d_in[21]; const float* fb1 = (const float*)d_in[22];
    const float* fw2 = (const float*)d_in[23]; const float* fb2 = (const float*)d_in[24];
    float* out = (float*)d_out;

    float *p_flat, *p_acc0, *p_h;
    cudaGetSymbolAddress((void**)&p_flat, g_flat);
    cudaGetSymbolAddress((void**)&p_acc0, g_acc0);
    cudaGetSymbolAddress((void**)&p_h,    g_h);

    const int convSmem = SM_TOTAL * 4 + WPK_TOTAL * 8;          // 192000 B
    const int preSmem  = (4096 + 4096 + 16384) * 4;             //  98304 B
    const int tailSmem = (8192 + 4096 + 4096 + 16384) * 4;      // 131072 B
    cudaFuncSetAttribute(conv_fused_kernel, cudaFuncAttributeMaxDynamicSharedMemorySize, convSmem);
    cudaFuncSetAttribute(pre_gcn_kernel,    cudaFuncAttributeMaxDynamicSharedMemorySize, preSmem);
    cudaFuncSetAttribute(gcn_tail_kernel,   cudaFuncAttributeMaxDynamicSharedMemorySize, tailSmem);

    zero_kernel<<<(BN*EDIM + 255)/256, 256>>>(p_acc0, BN*EDIM);

    conv_fused_kernel<<<BN, CONV_THREADS, convSmem>>>(states, cw0, cb0, cw1, cb1,
                                                      cw2, cb2, cw3, cb3, p_flat);

    mlp0_splitk_kernel<<<dim3(KSPLIT, BN/64), 256>>>(p_flat, mw0, p_acc0);

    pre_gcn_kernel<<<BN/32, 256, preSmem>>>(p_acc0, mb0, mw1, mb1, mw2, mb2, gw, p_h);

    gcn_tail_kernel<<<dim3(BATCH, 2), 256, tailSmem>>>(p_h, gb, fw0, fb0, fw1, fb1,
                                                       fw2, fb2, adj, inact, out);
}

// round 9
// speedup vs baseline: 1.2384x; 1.0279x over previous
#include <cuda_runtime.h>
#include <cuda_bf16.h>
#include <cstdint>

// ---------------------------------------------------------------------------
// Problem constants
// ---------------------------------------------------------------------------
#define BATCH   32
#define NAGENT  64
#define BN      2048
#define CIN0    16
#define HW0     30
#define FLAT    7744
#define EDIM    128
#define ADIM    5

// ---------------------------------------------------------------------------
// Scratch (activations between conv stages live in gmem / L2)
// ---------------------------------------------------------------------------
__device__ float g_a0   [ (size_t)BN * 16 * 28 * 28 ];   // 12544/agent
__device__ float g_a1   [ (size_t)BN * 32 * 26 * 26 ];   // 21632/agent
__device__ float g_a2   [ (size_t)BN * 16 * 24 * 24 ];   //  9216/agent
__device__ float g_flat [ (size_t)BN * FLAT ];           //  7744/agent
__device__ float g_acc0 [ BN * EDIM ];
__device__ float g_h    [ BN * EDIM ];

// ---------------------------------------------------------------------------
// f32x2 packed-math helpers
// ---------------------------------------------------------------------------
typedef unsigned long long u64;

__device__ __forceinline__ u64 pk2(float lo, float hi) {
    u64 r; asm("mov.b64 %0, {%1, %2};" : "=l"(r) : "f"(lo), "f"(hi)); return r;
}
__device__ __forceinline__ u64 pk1(float v) {
    u64 r; asm("mov.b64 %0, {%1, %1};" : "=l"(r) : "f"(v)); return r;
}
__device__ __forceinline__ u64 ffma2(u64 a, u64 b, u64 c) {
    u64 d; asm("fma.rn.f32x2 %0, %1, %2, %3;" : "=l"(d) : "l"(a), "l"(b), "l"(c));
    return d;
}
__device__ __forceinline__ void upk2(u64 v, float& lo, float& hi) {
    asm("mov.b64 {%0, %1}, %2;" : "=f"(lo), "=f"(hi) : "l"(v));
}

// ---------------------------------------------------------------------------
// Per-stage conv kernel.
//  grid = (BN, CO/COCH), block = (COCH/2)*OHW threads, ONE item per thread.
//  smem = input plane [CI][IHW][IHW] + packed weight chunk (u64 pairs).
//  Inner body identical to the proven R6 conv_stage2.
// ---------------------------------------------------------------------------
template<int CI, int CO, int COCH, int IHW, int OHW>
__global__ void __launch_bounds__((COCH/2)*OHW)
conv_stage_kernel(const float* __restrict__ in,   // [BN][CI][IHW][IHW]
                  float* __restrict__ out,        // [BN][CO][OHW][OHW]
                  const float* __restrict__ w,    // [CO][CI][9]
                  const float* __restrict__ bias) // [CO]
{
    extern __shared__ float s[];
    u64* wpk = (u64*)(s + CI * IHW * IHW);
    const int agent = blockIdx.x;
    const int coB   = blockIdx.y * COCH;
    const int tid   = threadIdx.x;
    constexpr int NTHR = (COCH / 2) * OHW;
    constexpr int PER  = CI * 9;

    // load input plane (coalesced float4)
    {
        const float4* src = (const float4*)(in + (size_t)agent * (CI * IHW * IHW));
        float4* dst = (float4*)s;
        #pragma unroll 4
        for (int i = tid; i < (CI * IHW * IHW) / 4; i += NTHR) dst[i] = src[i];
    }
    // pack this chunk's weights into u64 channel-pairs
    for (int i = tid; i < (COCH / 2) * PER; i += NTHR) {
        int pair = i / PER;
        int r    = i - pair * PER;
        wpk[i] = pk2(__ldg(&w[(size_t)(coB + 2 * pair    ) * PER + r]),
                     __ldg(&w[(size_t)(coB + 2 * pair + 1) * PER + r]));
    }
    __syncthreads();

    // exactly one work item per thread
    const int co2 = tid / OHW;          // pair index within chunk
    const int y   = tid - co2 * OHW;
    const int co  = coB + 2 * co2;

    u64 acc[OHW];
    u64 binit = pk2(__ldg(&bias[co]), __ldg(&bias[co + 1]));
    #pragma unroll
    for (int x = 0; x < OHW; x++) acc[x] = binit;

    const u64* wp0 = wpk + co2 * PER;

    for (int ci = 0; ci < CI; ci++) {
        #pragma unroll
        for (int ky = 0; ky < 3; ky++) {
            const u64* wp = wp0 + ci * 9 + ky * 3;
            u64 W0 = wp[0];
            u64 W1 = wp[1];
            u64 W2 = wp[2];
            const float* r = s + (ci * IHW + y + ky) * IHW;
            u64 b0 = pk1(r[0]);
            u64 b1 = pk1(r[1]);
            #pragma unroll
            for (int x = 0; x < OHW; x++) {
                u64 b2 = pk1(r[x + 2]);
                acc[x] = ffma2(b0, W0, acc[x]);
                acc[x] = ffma2(b1, W1, acc[x]);
                acc[x] = ffma2(b2, W2, acc[x]);
                b0 = b1; b1 = b2;
            }
        }
    }

    float* oA = out + ((size_t)agent * CO + co) * (OHW * OHW) + y * OHW;
    float* oB = oA + OHW * OHW;
    #pragma unroll
    for (int x = 0; x < OHW; x++) {
        float lo, hi; upk2(acc[x], lo, hi);
        oA[x] = fmaxf(lo, 0.0f);
        oB[x] = fmaxf(hi, 0.0f);
    }
}

// ---------------------------------------------------------------------------
// MLP0 split-K (unchanged from R6)
// ---------------------------------------------------------------------------
#define KSPLIT  8
#define KCHUNK  968

__global__ void mlp0_splitk_kernel(const float* __restrict__ A,
                                   const float* __restrict__ W,
                                   float* __restrict__ Cacc)
{
    __shared__ float As[8 * 68];
    __shared__ float Ws[8 * 128];
    const int t  = threadIdx.x;
    const int kz = blockIdx.x;
    const int m0 = blockIdx.y * 64;
    const int kstart = kz * KCHUNK;
    const int tx = t & 31, ty = t >> 5;

    u64 acc[8][2];
    #pragma unroll
    for (int r = 0; r < 8; r++) { acc[r][0] = 0ull; acc[r][1] = 0ull; }

    for (int kk = 0; kk < KCHUNK; kk += 8) {
        __syncthreads();
        {
            int e = t * 2;
            int m = e >> 3, k = e & 7;
            const float* ap = A + (size_t)(m0 + m) * FLAT + kstart + kk + k;
            As[ k      * 68 + m] = ap[0];
            As[(k + 1) * 68 + m] = ap[1];
        }
        {
            int e = t * 4;
            int k = e >> 7, col = e & 127;
            *(float4*)&Ws[k * 128 + col] =
                *(const float4*)&W[(size_t)(kstart + kk + k) * EDIM + col];
        }
        __syncthreads();
        #pragma unroll
        for (int k = 0; k < 8; k++) {
            u64 B0 = *(const u64*)&Ws[k * 128 + tx * 4];
            u64 B1 = *(const u64*)&Ws[k * 128 + tx * 4 + 2];
            float4 a0 = *(float4*)&As[k * 68 + ty * 8];
            float4 a1 = *(float4*)&As[k * 68 + ty * 8 + 4];
            float av[8] = {a0.x,a0.y,a0.z,a0.w,a1.x,a1.y,a1.z,a1.w};
            #pragma unroll
            for (int r = 0; r < 8; r++) {
                u64 ar = pk1(av[r]);
                acc[r][0] = ffma2(ar, B0, acc[r][0]);
                acc[r][1] = ffma2(ar, B1, acc[r][1]);
            }
        }
    }
    #pragma unroll
    for (int r = 0; r < 8; r++) {
        int m = m0 + ty * 8 + r;
        float v0, v1, v2, v3;
        upk2(acc[r][0], v0, v1);
        upk2(acc[r][1], v2, v3);
        atomicAdd(&Cacc[(size_t)m * EDIM + tx * 4 + 0], v0);
        atomicAdd(&Cacc[(size_t)m * EDIM + tx * 4 + 1], v1);
        atomicAdd(&Cacc[(size_t)m * EDIM + tx * 4 + 2], v2);
        atomicAdd(&Cacc[(size_t)m * EDIM + tx * 4 + 3], v3);
    }
}

// ---------------------------------------------------------------------------
// 32-row x 128 GEMM helper (256 threads): each thread 4 rows x 4 cols
// ---------------------------------------------------------------------------
__device__ __forceinline__ void gemm32(const float* __restrict__ sIn,
                                       float* __restrict__ sOut,
                                       float* __restrict__ sW,
                                       const float* __restrict__ W,
                                       const float* __restrict__ bias,
                                       int relu, int t)
{
    __syncthreads();
    for (int i = t * 4; i < 128 * 128; i += 1024)
        *(float4*)&sW[i] = *(const float4*)&W[i];
    __syncthreads();

    const int tx = t & 31;
    const int ry = (t >> 5) * 4;
    u64 acc[4][2];
    u64 b0i = bias ? pk2(bias[tx*4+0], bias[tx*4+1]) : 0ull;
    u64 b1i = bias ? pk2(bias[tx*4+2], bias[tx*4+3]) : 0ull;
    #pragma unroll
    for (int r = 0; r < 4; r++) { acc[r][0] = b0i; acc[r][1] = b1i; }

    #pragma unroll 4
    for (int k = 0; k < 128; k++) {
        u64 B0 = *(const u64*)&sW[k * 128 + tx * 4];
        u64 B1 = *(const u64*)&sW[k * 128 + tx * 4 + 2];
        #pragma unroll
        for (int r = 0; r < 4; r++) {
            u64 ar = pk1(sIn[(ry + r) * 128 + k]);
            acc[r][0] = ffma2(ar, B0, acc[r][0]);
            acc[r][1] = ffma2(ar, B1, acc[r][1]);
        }
    }
    #pragma unroll
    for (int r = 0; r < 4; r++) {
        float v[4];
        upk2(acc[r][0], v[0], v[1]);
        upk2(acc[r][1], v[2], v[3]);
        #pragma unroll
        for (int c = 0; c < 4; c++)
            if (relu) v[c] = fmaxf(v[c], 0.0f);
        *(float4*)&sOut[(ry + r) * 128 + tx * 4] = *(float4*)v;
    }
}

// ---------------------------------------------------------------------------
// K1: pre-GCN chain, grid = 64, 32-row tiles
// ---------------------------------------------------------------------------
__global__ __launch_bounds__(256, 1)
void pre_gcn_kernel(const float* __restrict__ acc0,
                    const float* __restrict__ mb0,
                    const float* __restrict__ mw1, const float* __restrict__ mb1,
                    const float* __restrict__ mw2, const float* __restrict__ mb2,
                    const float* __restrict__ gw,
                    float* __restrict__ h)
{
    extern __shared__ float s[];
    float* sA = s;             // 32*128
    float* sB = s + 4096;      // 32*128
    float* sW = s + 8192;      // 128*128
    const int t = threadIdx.x;
    const size_t base = (size_t)blockIdx.x * 32 * EDIM;

    for (int i = t; i < 4096; i += 256) {
        int k = i & 127;
        sA[i] = fmaxf(acc0[base + i] + mb0[k], 0.0f);
    }

    gemm32(sA, sB, sW, mw1, mb1, 1, t);
    gemm32(sB, sA, sW, mw2, mb2, 0, t);
    gemm32(sA, sB, sW, gw,  nullptr, 0, t);

    __syncthreads();
    for (int i = t; i < 4096; i += 256) h[base + i] = sB[i];
}

// ---------------------------------------------------------------------------
// K2: GCN aggregation + DQN head, grid = (32 batches, 2 halves of 32 agents)
// ---------------------------------------------------------------------------
__global__ __launch_bounds__(256, 1)
void gcn_tail_kernel(const float* __restrict__ h,
                     const float* __restrict__ gb,
                     const float* __restrict__ fw0, const float* __restrict__ fb0,
                     const float* __restrict__ fw1, const float* __restrict__ fb1,
                     const float* __restrict__ fw2, const float* __restrict__ fb2,
                     const float* __restrict__ adj,
                     const int* __restrict__ inact,
                     float* __restrict__ out)
{
    extern __shared__ float s[];
    float* sH = s;            // 64*128
    float* sX = s + 8192;     // 32*128
    float* sY = s + 12288;    // 32*128
    float* sW = s + 16384;    // 128*128; adj(4096)+dis(64) scratch
    const int b = blockIdx.x, t = threadIdx.x;
    const int j0 = blockIdx.y * 32;
    const size_t row0 = (size_t)b * NAGENT;

    for (int i = t; i < 8192; i += 256) sH[i] = h[row0 * EDIM + i];
    for (int i = t; i < 4096; i += 256) sW[i] = adj[(size_t)b * 4096 + i];
    __syncthreads();
    if (t < 64) {
        float d = 0.f;
        for (int i = 0; i < 64; i++) d += sW[i * 64 + t];
        sW[4096 + t] = (d > 0.f) ? rsqrtf(fmaxf(d, 1e-30f)) : 0.f;
    }
    __syncthreads();
    for (int i = t; i < 4096; i += 256) {
        int r = i >> 6, c = i & 63;
        sW[i] *= sW[4096 + r] * sW[4096 + c];
    }
    __syncthreads();
    for (int o = t; o < 4096; o += 256) {
        int jl = o >> 7, d = o & 127;
        int j = j0 + jl;
        float a = gb[d];
        #pragma unroll 8
        for (int i = 0; i < 64; i++)
            a = fmaf(sW[i * 64 + j], sH[i * 128 + d], a);
        sX[o] = a;
    }

    gemm32(sX, sY, sW, fw0, fb0, 1, t);   // q1
    gemm32(sY, sX, sW, fw1, fb1, 1, t);   // q2

    __syncthreads();
    for (int p = t; p < 32 * ADIM; p += 256) {
        int row = p / ADIM, a = p - row * ADIM;
        float acc = fb2[a];
        #pragma unroll 8
        for (int k = 0; k < EDIM; k++)
            acc = fmaf(sX[row * 128 + k], __ldg(&fw2[k * ADIM + a]), acc);
        size_t grow = row0 + j0 + row;
        bool z = (inact[grow] != 0);
        out[grow * ADIM + a] = z ? 0.f : acc;
    }
}

__global__ void zero_kernel(float* __restrict__ p, int n)
{
    int i = blockIdx.x * blockDim.x + threadIdx.x;
    if (i < n) p[i] = 0.f;
}

// ---------------------------------------------------------------------------
// Launch
// ---------------------------------------------------------------------------
extern "C" void kernel_launch(void* const* d_in, const int* in_sizes, int n_in,
                              void* d_out, int out_size)
{
    (void)in_sizes; (void)n_in; (void)out_size;
    const float* states = (const float*)d_in[0];
    const float* adj    = (const float*)d_in[1];
    const int*   inact  = (const int*)d_in[2];
    const float* cw0 = (const float*)d_in[3];  const float* cb0 = (const float*)d_in[4];
    const float* cw1 = (const float*)d_in[5];  const float* cb1 = (const float*)d_in[6];
    const float* cw2 = (const float*)d_in[7];  const float* cb2 = (const float*)d_in[8];
    const float* cw3 = (const float*)d_in[9];  const float* cb3 = (const float*)d_in[10];
    const float* mw0 = (const float*)d_in[11]; const float* mb0 = (const float*)d_in[12];
    const float* mw1 = (const float*)d_in[13]; const float* mb1 = (const float*)d_in[14];
    const float* mw2 = (const float*)d_in[15]; const float* mb2 = (const float*)d_in[16];
    const float* gw  = (const float*)d_in[17]; const float* gb  = (const float*)d_in[18];
    const float* fw0 = (const float*)d_in[19]; const float* fb0 = (const float*)d_in[20];
    const float* fw1 = (const float*)d_in[21]; const float* fb1 = (const float*)d_in[22];
    const float* fw2 = (const float*)d_in[23]; const float* fb2 = (const float*)d_in[24];
    float* out = (float*)d_out;

    float *p_a0, *p_a1, *p_a2, *p_flat, *p_acc0, *p_h;
    cudaGetSymbolAddress((void**)&p_a0,   g_a0);
    cudaGetSymbolAddress((void**)&p_a1,   g_a1);
    cudaGetSymbolAddress((void**)&p_a2,   g_a2);
    cudaGetSymbolAddress((void**)&p_flat, g_flat);
    cudaGetSymbolAddress((void**)&p_acc0, g_acc0);
    cudaGetSymbolAddress((void**)&p_h,    g_h);

    // per-stage smem: input plane + packed weight chunk
    const int smem0 = 16*30*30*4 + (8*16*9)*8;   // 57600 + 9216  = 66816
    const int smem1 = 16*28*28*4 + (8*16*9)*8;   // 50176 + 9216  = 59392
    const int smem2 = 32*26*26*4 + (8*32*9)*8;   // 86528 + 18432 = 104960
    const int smem3 = 16*24*24*4 + (8*16*9)*8;   // 36864 + 9216  = 46080
    const int preSmem  = (4096 + 4096 + 16384) * 4;
    const int tailSmem = (8192 + 4096 + 4096 + 16384) * 4;

    cudaFuncSetAttribute((const void*)conv_stage_kernel<16,16,16,30,28>,
                         cudaFuncAttributeMaxDynamicSharedMemorySize, smem0);
    cudaFuncSetAttribute((const void*)conv_stage_kernel<16,32,16,28,26>,
                         cudaFuncAttributeMaxDynamicSharedMemorySize, smem1);
    cudaFuncSetAttribute((const void*)conv_stage_kernel<32,16,16,26,24>,
                         cudaFuncAttributeMaxDynamicSharedMemorySize, smem2);
    cudaFuncSetAttribute((const void*)conv_stage_kernel<16,16,16,24,22>,
                         cudaFuncAttributeMaxDynamicSharedMemorySize, smem3);
    cudaFuncSetAttribute(pre_gcn_kernel,  cudaFuncAttributeMaxDynamicSharedMemorySize, preSmem);
    cudaFuncSetAttribute(gcn_tail_kernel, cudaFuncAttributeMaxDynamicSharedMemorySize, tailSmem);

    zero_kernel<<<(BN*EDIM + 255)/256, 256>>>(p_acc0, BN*EDIM);

    // conv stages (one item per thread; block = (COCH/2)*OHW)
    conv_stage_kernel<16,16,16,30,28><<<dim3(BN,1), 224, smem0>>>(states, p_a0, cw0, cb0);
    conv_stage_kernel<16,32,16,28,26><<<dim3(BN,2), 208, smem1>>>(p_a0,   p_a1, cw1, cb1);
    conv_stage_kernel<32,16,16,26,24><<<dim3(BN,1), 192, smem2>>>(p_a1,   p_a2, cw2, cb2);
    conv_stage_kernel<16,16,16,24,22><<<dim3(BN,1), 176, smem3>>>(p_a2, p_flat, cw3, cb3);

    mlp0_splitk_kernel<<<dim3(KSPLIT, BN/64), 256>>>(p_flat, mw0, p_acc0);

    pre_gcn_kernel<<<BN/32, 256, preSmem>>>(p_acc0, mb0, mw1, mb1, mw2, mb2, gw, p_h);

    gcn_tail_kernel<<<dim3(BATCH, 2), 256, tailSmem>>>(p_h, gb, fw0, fb0, fw1, fb1,
                                                       fw2, fb2, adj, inact, out);
}